// round 2
// baseline (speedup 1.0000x reference)
#include <cuda_runtime.h>

#define BB 16
#define LL 200
#define HH 64
#define NHEAD 2
#define DD 32

// Scratch (no cudaMalloc allowed)
__device__ float g_Qp[BB * LL * HH];
__device__ float g_KpK[BB * LL * HH];
__device__ float g_VpV[BB * LL * HH];
__device__ int   g_mask_is_u8;   // 1 if masks stored as uint8, 0 if int32

// ---------------------------------------------------------------------------
// Detect mask storage dtype from attn_mask buffer content.
// int32 storage: every 4-byte word is 0 or 1.
// uint8 storage: words pack 4 random bools -> some word > 1 almost surely.
// ---------------------------------------------------------------------------
__global__ void detect_mask_kernel(const unsigned int* __restrict__ am_words)
{
    __shared__ int found;
    if (threadIdx.x == 0) found = 0;
    __syncthreads();
    for (int i = threadIdx.x; i < 10000; i += blockDim.x)
        if (am_words[i] > 1u) found = 1;
    __syncthreads();
    if (threadIdx.x == 0) g_mask_is_u8 = found;
}

__device__ __forceinline__ bool read_mask(const void* p, int i, int is_u8)
{
    return is_u8 ? (((const unsigned char*)p)[i] != 0)
                 : (((const int*)p)[i] != 0);
}

// ---------------------------------------------------------------------------
// Prep: Qp = queries@Wq^T + bq ; KpK = keys@Wk^T + bk + abs_pos_K ;
//       VpV = keys@Wv^T + bv + abs_pos_V.   One block per (b,l) row, 64 thr.
// ---------------------------------------------------------------------------
__global__ __launch_bounds__(64) void prep_kernel(
    const float* __restrict__ queries, const float* __restrict__ keys,
    const float* __restrict__ abs_pos_K, const float* __restrict__ abs_pos_V,
    const float* __restrict__ Wq, const float* __restrict__ bq,
    const float* __restrict__ Wk, const float* __restrict__ bk,
    const float* __restrict__ Wv, const float* __restrict__ bv)
{
    int row = blockIdx.x;          // 0 .. B*L-1
    int c   = threadIdx.x;         // output column 0..63
    __shared__ float xq[HH], xk[HH];
    xq[c] = queries[row * HH + c];
    xk[c] = keys[row * HH + c];
    __syncthreads();

    float aq = 0.f, ak = 0.f, av = 0.f;
#pragma unroll 8
    for (int j = 0; j < HH; ++j) {
        float qv = xq[j], kv = xk[j];
        aq += qv * Wq[c * HH + j];
        ak += kv * Wk[c * HH + j];
        av += kv * Wv[c * HH + j];
    }
    int o = row * HH + c;
    g_Qp[o]  = aq + bq[c];
    g_KpK[o] = ak + bk[c] + abs_pos_K[o];
    g_VpV[o] = av + bv[c] + abs_pos_V[o];
}

// ---------------------------------------------------------------------------
// Fused attention: one CTA per (b,q), 256 threads (8 warps).
// ---------------------------------------------------------------------------
__global__ __launch_bounds__(256) void attn_kernel(
    const float* __restrict__ tK, const float* __restrict__ dK,
    const float* __restrict__ tV, const float* __restrict__ dV,
    const void* __restrict__ time_mask,
    const void* __restrict__ attn_mask,
    float* __restrict__ out)
{
    const int bq = blockIdx.x;         // b*L + q
    const int b  = bq / LL;
    const int q  = bq % LL;
    const int t    = threadIdx.x;
    const int warp = t >> 5;
    const int lane = t & 31;

    __shared__ float s_attn[NHEAD][LL];
    __shared__ float s_inv[NHEAD];
    __shared__ unsigned char s_am[LL];
    __shared__ float s_part[3][HH];

    const int is_u8 = g_mask_is_u8;
    if (t < LL) s_am[t] = read_mask(attn_mask, q * LL + t, is_u8) ? 1 : 0;
    const bool tmq = read_mask(time_mask, b * LL + q, is_u8);

    // Q row (both heads), one lane per channel
    const float* Qrow = g_Qp + bq * HH;
    const float q0 = Qrow[lane];
    const float q1 = Qrow[32 + lane];
    __syncthreads();

    const float scale = 0.17677669529663687f;   // 1/sqrt(32)
    const float NEGV  = -4294967295.0f;         // -2^32 + 1

    const int base_qk = bq * LL * HH;           // < 2^31, fits int

    // ---- K phase: scores for both heads ----
    for (int k = warp; k < LL; k += 8) {
        const int off  = base_qk + k * HH;
        const int koff = (b * LL + k) * HH;
        float v0 = tK[off + lane]      + dK[off + lane]      + g_KpK[koff + lane];
        float v1 = tK[off + 32 + lane] + dK[off + 32 + lane] + g_KpK[koff + 32 + lane];
        float p0 = v0 * q0;
        float p1 = v1 * q1;
#pragma unroll
        for (int s = 16; s > 0; s >>= 1) {
            p0 += __shfl_xor_sync(0xffffffffu, p0, s);
            p1 += __shfl_xor_sync(0xffffffffu, p1, s);
        }
        if (lane == 0) {
            bool m = tmq || (s_am[k] != 0);
            s_attn[0][k] = m ? NEGV : p0 * scale;
            s_attn[1][k] = m ? NEGV : p1 * scale;
        }
    }
    __syncthreads();

    // ---- softmax: warp h handles head h ----
    if (warp < NHEAD) {
        float m = -3.4e38f;
        for (int k = lane; k < LL; k += 32) m = fmaxf(m, s_attn[warp][k]);
#pragma unroll
        for (int s = 16; s > 0; s >>= 1)
            m = fmaxf(m, __shfl_xor_sync(0xffffffffu, m, s));
        float sum = 0.f;
        for (int k = lane; k < LL; k += 32) {
            float e = __expf(s_attn[warp][k] - m);
            s_attn[warp][k] = e;                 // unnormalized
            sum += e;
        }
#pragma unroll
        for (int s = 16; s > 0; s >>= 1)
            sum += __shfl_xor_sync(0xffffffffu, sum, s);
        if (lane == 0) s_inv[warp] = 1.0f / sum;
    }
    __syncthreads();

    // ---- V phase: 4 k-groups x 64 (head,channel) threads ----
    const int g  = t >> 6;       // 0..3
    const int hd = t & 63;       // h*32 + dd
    const int h  = hd >> 5;
    const float inv = s_inv[h];

    float acc = 0.f;
#pragma unroll 5
    for (int k = g; k < LL; k += 4) {
        const float a   = s_attn[h][k];
        const int off   = base_qk + k * HH + hd;
        const int koff  = (b * LL + k) * HH + hd;
        acc += a * (tV[off] + dV[off] + g_VpV[koff]);
    }
    if (g > 0) s_part[g - 1][hd] = acc;
    __syncthreads();
    if (g == 0) {
        acc += s_part[0][hd] + s_part[1][hd] + s_part[2][hd];
        out[bq * HH + hd] = acc * inv;
    }
}

// ---------------------------------------------------------------------------
extern "C" void kernel_launch(void* const* d_in, const int* in_sizes, int n_in,
                              void* d_out, int out_size)
{
    const float* queries  = (const float*)d_in[0];
    const float* keys     = (const float*)d_in[1];
    const void*  time_mask = d_in[2];
    const void*  attn_mask = d_in[3];
    const float* tK = (const float*)d_in[4];
    const float* tV = (const float*)d_in[5];
    const float* dK = (const float*)d_in[6];
    const float* dV = (const float*)d_in[7];
    const float* abs_pos_K = (const float*)d_in[8];
    const float* abs_pos_V = (const float*)d_in[9];
    const float* Wq = (const float*)d_in[10];
    const float* bq = (const float*)d_in[11];
    const float* Wk = (const float*)d_in[12];
    const float* bk = (const float*)d_in[13];
    const float* Wv = (const float*)d_in[14];
    const float* bv = (const float*)d_in[15];
    float* out = (float*)d_out;

    detect_mask_kernel<<<1, 256>>>((const unsigned int*)attn_mask);
    prep_kernel<<<BB * LL, 64>>>(queries, keys, abs_pos_K, abs_pos_V,
                                 Wq, bq, Wk, bk, Wv, bv);
    attn_kernel<<<BB * LL, 256>>>(tK, dK, tV, dV, time_mask, attn_mask, out);
}

// round 3
// speedup vs baseline: 1.2392x; 1.2392x over previous
#include <cuda_runtime.h>

#define BB 16
#define LL 200
#define HH 64
#define NHEAD 2

__device__ float g_Qp[BB * LL * HH];
__device__ float g_KpK[BB * LL * HH];
__device__ float g_VpV[BB * LL * HH];
__device__ int   g_mask_is_u8;   // 1 if masks stored as uint8, 0 if int32

__device__ __forceinline__ bool read_mask(const void* p, int i, int is_u8)
{
    return is_u8 ? (((const unsigned char*)p)[i] != 0)
                 : (((const int*)p)[i] != 0);
}

// ---------------------------------------------------------------------------
// Prep: Qp = queries@Wq^T + bq ; KpK = keys@Wk^T + bk + abs_pos_K ;
//       VpV = keys@Wv^T + bv + abs_pos_V.  One block per (b,l) row, 64 thr.
// Block 0 additionally detects mask storage dtype (int32 vs uint8).
// ---------------------------------------------------------------------------
__global__ __launch_bounds__(64) void prep_kernel(
    const float* __restrict__ queries, const float* __restrict__ keys,
    const float* __restrict__ abs_pos_K, const float* __restrict__ abs_pos_V,
    const float* __restrict__ Wq, const float* __restrict__ bq,
    const float* __restrict__ Wk, const float* __restrict__ bk,
    const float* __restrict__ Wv, const float* __restrict__ bv,
    const unsigned int* __restrict__ am_words)
{
    int row = blockIdx.x;
    int c   = threadIdx.x;

    if (row == 0) {
        // uint8 storage packs 4 random bools/word -> some word > 1 a.s.
        unsigned int bad = 0;
        for (int i = c; i < 256; i += 64) bad |= (am_words[i] > 1u);
        unsigned int any = __ballot_sync(0xffffffffu, bad != 0);
        if (c == 0) g_mask_is_u8 = (any != 0) ? 1 : 0;
    }

    __shared__ float xq[HH], xk[HH];
    xq[c] = queries[row * HH + c];
    xk[c] = keys[row * HH + c];
    __syncthreads();

    float aq = 0.f, ak = 0.f, av = 0.f;
#pragma unroll 8
    for (int j = 0; j < HH; ++j) {
        float qv = xq[j], kv = xk[j];
        aq += qv * Wq[c * HH + j];
        ak += kv * Wk[c * HH + j];
        av += kv * Wv[c * HH + j];
    }
    int o = row * HH + c;
    g_Qp[o]  = aq + bq[c];
    g_KpK[o] = ak + bk[c] + abs_pos_K[o];
    g_VpV[o] = av + bv[c] + abs_pos_V[o];
}

// ---------------------------------------------------------------------------
// Fused attention: one CTA per (b,q), 256 threads, float4 streaming.
// ---------------------------------------------------------------------------
__global__ __launch_bounds__(256) void attn_kernel(
    const float* __restrict__ tK, const float* __restrict__ dK,
    const float* __restrict__ tV, const float* __restrict__ dV,
    const void* __restrict__ time_mask,
    const void* __restrict__ attn_mask,
    float* __restrict__ out)
{
    const int bq = blockIdx.x;
    const int b  = bq / LL;
    const int q  = bq % LL;
    const int t    = threadIdx.x;
    const int warp = t >> 5;
    const int lane = t & 31;

    __shared__ float s_attn[NHEAD][LL];
    __shared__ float s_inv[NHEAD];
    __shared__ unsigned char s_am[LL];
    __shared__ float4 s_red[16][16];

    const int is_u8 = g_mask_is_u8;
    if (t < LL) s_am[t] = read_mask(attn_mask, q * LL + t, is_u8) ? 1 : 0;
    const bool tmq = read_mask(time_mask, b * LL + q, is_u8);

    const float scale = 0.17677669529663687f;   // 1/sqrt(32)
    const float NEGV  = -4294967295.0f;         // -2^32 + 1

    // ---- K phase: float4, 2 k-rows per warp per iter ----
    {
        const int sub  = lane >> 4;       // which of the 2 k rows
        const int idx4 = lane & 15;       // float4 index within row (16 per row)
        const int head = idx4 >> 3;

        const float4* Qrow4 = (const float4*)g_Qp + bq * 16;
        const float4  q4    = Qrow4[idx4];
        const float4* tK4   = (const float4*)tK + (size_t)bq * LL * 16;
        const float4* dK4   = (const float4*)dK + (size_t)bq * LL * 16;
        const float4* KpK4  = (const float4*)g_KpK + b * LL * 16;

        __syncthreads();   // s_am ready (needed by lane writes below)

#pragma unroll
        for (int i = 0; i < 13; ++i) {
            int kb = (i * 8 + warp) * 2;
            if (kb < LL) {
                int k = kb + sub;
                int o = k * 16 + idx4;
                float4 tv = __ldcs(tK4 + o);
                float4 dv = __ldcs(dK4 + o);
                float4 kp = KpK4[o];
                float p = (tv.x + dv.x + kp.x) * q4.x
                        + (tv.y + dv.y + kp.y) * q4.y
                        + (tv.z + dv.z + kp.z) * q4.z
                        + (tv.w + dv.w + kp.w) * q4.w;
                p += __shfl_xor_sync(0xffffffffu, p, 1);
                p += __shfl_xor_sync(0xffffffffu, p, 2);
                p += __shfl_xor_sync(0xffffffffu, p, 4);
                if ((lane & 7) == 0) {
                    bool m = tmq || (s_am[k] != 0);
                    s_attn[head][k] = m ? NEGV : p * scale;
                }
            }
        }
    }
    __syncthreads();

    // ---- softmax: warp h handles head h ----
    if (warp < NHEAD) {
        float m = -3.4e38f;
        for (int k = lane; k < LL; k += 32) m = fmaxf(m, s_attn[warp][k]);
#pragma unroll
        for (int s = 16; s > 0; s >>= 1)
            m = fmaxf(m, __shfl_xor_sync(0xffffffffu, m, s));
        float sum = 0.f;
        for (int k = lane; k < LL; k += 32) {
            float e = __expf(s_attn[warp][k] - m);
            s_attn[warp][k] = e;                 // unnormalized
            sum += e;
        }
#pragma unroll
        for (int s = 16; s > 0; s >>= 1)
            sum += __shfl_xor_sync(0xffffffffu, sum, s);
        if (lane == 0) s_inv[warp] = 1.0f / sum;
    }
    __syncthreads();

    // ---- V phase: float4, 16 k-rows per CTA per iter ----
    {
        const int g    = t >> 4;          // 0..15: k group
        const int idx4 = t & 15;          // float4 index within row
        const int head = idx4 >> 3;

        const float4* tV4  = (const float4*)tV + (size_t)bq * LL * 16;
        const float4* dV4  = (const float4*)dV + (size_t)bq * LL * 16;
        const float4* VpV4 = (const float4*)g_VpV + b * LL * 16;

        float4 acc = make_float4(0.f, 0.f, 0.f, 0.f);
#pragma unroll
        for (int i = 0; i < 13; ++i) {
            int k = i * 16 + g;
            if (k < LL) {
                float a = s_attn[head][k];
                int o = k * 16 + idx4;
                float4 tv = __ldcs(tV4 + o);
                float4 dv = __ldcs(dV4 + o);
                float4 vp = VpV4[o];
                acc.x += a * (tv.x + dv.x + vp.x);
                acc.y += a * (tv.y + dv.y + vp.y);
                acc.z += a * (tv.z + dv.z + vp.z);
                acc.w += a * (tv.w + dv.w + vp.w);
            }
        }
        s_red[g][idx4] = acc;
    }
    __syncthreads();

    if (t < HH) {
        const int idx4 = t >> 2;
        const int c    = t & 3;
        const float inv = s_inv[t >> 5];
        float sum = 0.f;
#pragma unroll
        for (int g = 0; g < 16; ++g) {
            const float* v = (const float*)&s_red[g][idx4];
            sum += v[c];
        }
        out[bq * HH + t] = sum * inv;
    }
}

// ---------------------------------------------------------------------------
extern "C" void kernel_launch(void* const* d_in, const int* in_sizes, int n_in,
                              void* d_out, int out_size)
{
    const float* queries  = (const float*)d_in[0];
    const float* keys     = (const float*)d_in[1];
    const void*  time_mask = d_in[2];
    const void*  attn_mask = d_in[3];
    const float* tK = (const float*)d_in[4];
    const float* tV = (const float*)d_in[5];
    const float* dK = (const float*)d_in[6];
    const float* dV = (const float*)d_in[7];
    const float* abs_pos_K = (const float*)d_in[8];
    const float* abs_pos_V = (const float*)d_in[9];
    const float* Wq = (const float*)d_in[10];
    const float* bq = (const float*)d_in[11];
    const float* Wk = (const float*)d_in[12];
    const float* bk = (const float*)d_in[13];
    const float* Wv = (const float*)d_in[14];
    const float* bv = (const float*)d_in[15];
    float* out = (float*)d_out;

    prep_kernel<<<BB * LL, 64>>>(queries, keys, abs_pos_K, abs_pos_V,
                                 Wq, bq, Wk, bk, Wv, bv,
                                 (const unsigned int*)attn_mask);
    attn_kernel<<<BB * LL, 256>>>(tK, dK, tV, dV, time_mask, attn_mask, out);
}

// round 4
// speedup vs baseline: 2.6167x; 2.1116x over previous
#include <cuda_runtime.h>

#define BB 16
#define LL 200
#define HH 64
#define NHEAD 2
#define ROWS_PB 4   // (b,l) rows per prep block

__device__ float g_Qp[BB * LL * HH];
__device__ float g_KpK[BB * LL * HH];
__device__ float g_VpV[BB * LL * HH];
__device__ int   g_mask_is_u8;   // 1 if masks stored as uint8, 0 if int32

__device__ __forceinline__ bool read_mask(const void* p, int i, int is_u8)
{
    return is_u8 ? (((const unsigned char*)p)[i] != 0)
                 : (((const int*)p)[i] != 0);
}

// ---------------------------------------------------------------------------
// Prep: Qp = queries@Wq^T + bq ; KpK = keys@Wk^T + bk + abs_pos_K ;
//       VpV = keys@Wv^T + bv + abs_pos_V.
// 256 threads, 4 rows per block; W staged in padded smem (conflict-free).
// Block 0 additionally detects mask storage dtype (int32 vs uint8).
// ---------------------------------------------------------------------------
__global__ __launch_bounds__(256) void prep_kernel(
    const float* __restrict__ queries, const float* __restrict__ keys,
    const float* __restrict__ abs_pos_K, const float* __restrict__ abs_pos_V,
    const float* __restrict__ Wq, const float* __restrict__ bq,
    const float* __restrict__ Wk, const float* __restrict__ bk,
    const float* __restrict__ Wv, const float* __restrict__ bv,
    const unsigned int* __restrict__ am_words)
{
    const int t = threadIdx.x;

    if (blockIdx.x == 0 && t < 64) {
        // uint8 storage packs 4 random bools/word -> some word > 1 a.s.
        unsigned int bad = 0;
        for (int i = t; i < 256; i += 64) bad |= (am_words[i] > 1u);
        unsigned int any = __ballot_sync(0xffffffffu, bad != 0);
        if (t == 0) g_mask_is_u8 = (any != 0) ? 1 : 0;
    }

    __shared__ float Wqs[HH][HH + 1];
    __shared__ float Wks[HH][HH + 1];
    __shared__ float Wvs[HH][HH + 1];
    __shared__ float xq[ROWS_PB][HH];
    __shared__ float xk[ROWS_PB][HH];

    // Coalesced cooperative load of the three 64x64 weight matrices.
#pragma unroll
    for (int i = 0; i < 16; ++i) {
        int idx = i * 256 + t;           // 0..4095
        int r = idx >> 6, c = idx & 63;
        Wqs[r][c] = Wq[idx];
        Wks[r][c] = Wk[idx];
        Wvs[r][c] = Wv[idx];
    }

    const int r = t >> 6;                // row within block, 0..3
    const int c = t & 63;                // output column
    const int row = blockIdx.x * ROWS_PB + r;
    xq[r][c] = queries[row * HH + c];
    xk[r][c] = keys[row * HH + c];
    __syncthreads();

    float aq = 0.f, ak = 0.f, av = 0.f;
#pragma unroll 16
    for (int j = 0; j < HH; ++j) {
        float qv = xq[r][j], kv = xk[r][j];
        aq += qv * Wqs[c][j];
        ak += kv * Wks[c][j];
        av += kv * Wvs[c][j];
    }
    const int o = row * HH + c;
    g_Qp[o]  = aq + bq[c];
    g_KpK[o] = ak + bk[c] + abs_pos_K[o];
    g_VpV[o] = av + bv[c] + abs_pos_V[o];
}

// ---------------------------------------------------------------------------
// Fused attention: one CTA per (b,q), 256 threads, float4 streaming.
// (84% DRAM on R3 profile — unchanged.)
// ---------------------------------------------------------------------------
__global__ __launch_bounds__(256) void attn_kernel(
    const float* __restrict__ tK, const float* __restrict__ dK,
    const float* __restrict__ tV, const float* __restrict__ dV,
    const void* __restrict__ time_mask,
    const void* __restrict__ attn_mask,
    float* __restrict__ out)
{
    const int bq = blockIdx.x;
    const int b  = bq / LL;
    const int q  = bq % LL;
    const int t    = threadIdx.x;
    const int warp = t >> 5;
    const int lane = t & 31;

    __shared__ float s_attn[NHEAD][LL];
    __shared__ float s_inv[NHEAD];
    __shared__ unsigned char s_am[LL];
    __shared__ float4 s_red[16][16];

    const int is_u8 = g_mask_is_u8;
    if (t < LL) s_am[t] = read_mask(attn_mask, q * LL + t, is_u8) ? 1 : 0;
    const bool tmq = read_mask(time_mask, b * LL + q, is_u8);

    const float scale = 0.17677669529663687f;   // 1/sqrt(32)
    const float NEGV  = -4294967295.0f;         // -2^32 + 1

    // ---- K phase: float4, 2 k-rows per warp per iter ----
    {
        const int sub  = lane >> 4;
        const int idx4 = lane & 15;
        const int head = idx4 >> 3;

        const float4* Qrow4 = (const float4*)g_Qp + bq * 16;
        const float4  q4    = Qrow4[idx4];
        const float4* tK4   = (const float4*)tK + (size_t)bq * LL * 16;
        const float4* dK4   = (const float4*)dK + (size_t)bq * LL * 16;
        const float4* KpK4  = (const float4*)g_KpK + b * LL * 16;

        __syncthreads();   // s_am ready

#pragma unroll
        for (int i = 0; i < 13; ++i) {
            int kb = (i * 8 + warp) * 2;
            if (kb < LL) {
                int k = kb + sub;
                int o = k * 16 + idx4;
                float4 tv = __ldcs(tK4 + o);
                float4 dv = __ldcs(dK4 + o);
                float4 kp = KpK4[o];
                float p = (tv.x + dv.x + kp.x) * q4.x
                        + (tv.y + dv.y + kp.y) * q4.y
                        + (tv.z + dv.z + kp.z) * q4.z
                        + (tv.w + dv.w + kp.w) * q4.w;
                p += __shfl_xor_sync(0xffffffffu, p, 1);
                p += __shfl_xor_sync(0xffffffffu, p, 2);
                p += __shfl_xor_sync(0xffffffffu, p, 4);
                if ((lane & 7) == 0) {
                    bool m = tmq || (s_am[k] != 0);
                    s_attn[head][k] = m ? NEGV : p * scale;
                }
            }
        }
    }
    __syncthreads();

    // ---- softmax: warp h handles head h ----
    if (warp < NHEAD) {
        float m = -3.4e38f;
        for (int k = lane; k < LL; k += 32) m = fmaxf(m, s_attn[warp][k]);
#pragma unroll
        for (int s = 16; s > 0; s >>= 1)
            m = fmaxf(m, __shfl_xor_sync(0xffffffffu, m, s));
        float sum = 0.f;
        for (int k = lane; k < LL; k += 32) {
            float e = __expf(s_attn[warp][k] - m);
            s_attn[warp][k] = e;                 // unnormalized
            sum += e;
        }
#pragma unroll
        for (int s = 16; s > 0; s >>= 1)
            sum += __shfl_xor_sync(0xffffffffu, sum, s);
        if (lane == 0) s_inv[warp] = 1.0f / sum;
    }
    __syncthreads();

    // ---- V phase: float4, 16 k-rows per CTA per iter ----
    {
        const int g    = t >> 4;
        const int idx4 = t & 15;
        const int head = idx4 >> 3;

        const float4* tV4  = (const float4*)tV + (size_t)bq * LL * 16;
        const float4* dV4  = (const float4*)dV + (size_t)bq * LL * 16;
        const float4* VpV4 = (const float4*)g_VpV + b * LL * 16;

        float4 acc = make_float4(0.f, 0.f, 0.f, 0.f);
#pragma unroll
        for (int i = 0; i < 13; ++i) {
            int k = i * 16 + g;
            if (k < LL) {
                float a = s_attn[head][k];
                int o = k * 16 + idx4;
                float4 tv = __ldcs(tV4 + o);
                float4 dv = __ldcs(dV4 + o);
                float4 vp = VpV4[o];
                acc.x += a * (tv.x + dv.x + vp.x);
                acc.y += a * (tv.y + dv.y + vp.y);
                acc.z += a * (tv.z + dv.z + vp.z);
                acc.w += a * (tv.w + dv.w + vp.w);
            }
        }
        s_red[g][idx4] = acc;
    }
    __syncthreads();

    if (t < HH) {
        const int idx4 = t >> 2;
        const int c    = t & 3;
        const float inv = s_inv[t >> 5];
        float sum = 0.f;
#pragma unroll
        for (int g = 0; g < 16; ++g) {
            const float* v = (const float*)&s_red[g][idx4];
            sum += v[c];
        }
        out[bq * HH + t] = sum * inv;
    }
}

// ---------------------------------------------------------------------------
extern "C" void kernel_launch(void* const* d_in, const int* in_sizes, int n_in,
                              void* d_out, int out_size)
{
    const float* queries  = (const float*)d_in[0];
    const float* keys     = (const float*)d_in[1];
    const void*  time_mask = d_in[2];
    const void*  attn_mask = d_in[3];
    const float* tK = (const float*)d_in[4];
    const float* tV = (const float*)d_in[5];
    const float* dK = (const float*)d_in[6];
    const float* dV = (const float*)d_in[7];
    const float* abs_pos_K = (const float*)d_in[8];
    const float* abs_pos_V = (const float*)d_in[9];
    const float* Wq = (const float*)d_in[10];
    const float* bq = (const float*)d_in[11];
    const float* Wk = (const float*)d_in[12];
    const float* bk = (const float*)d_in[13];
    const float* Wv = (const float*)d_in[14];
    const float* bv = (const float*)d_in[15];
    float* out = (float*)d_out;

    prep_kernel<<<BB * LL / ROWS_PB, 256>>>(queries, keys, abs_pos_K, abs_pos_V,
                                            Wq, bq, Wk, bk, Wv, bv,
                                            (const unsigned int*)attn_mask);
    attn_kernel<<<BB * LL, 256>>>(tK, dK, tV, dV, time_mask, attn_mask, out);
}

// round 6
// speedup vs baseline: 4.0352x; 1.5421x over previous
#include <cuda_runtime.h>

#define BB 16
#define LL 200
#define HH 64
#define NHEAD 2
#define ROWS_PB 4   // (b,l) rows per prep block

__device__ float g_Qp[BB * LL * HH];
__device__ float g_KpK[BB * LL * HH];
__device__ float g_VpV[BB * LL * HH];
__device__ int   g_mask_is_u8;   // 1 if masks stored as uint8, 0 if int32

__device__ __forceinline__ bool read_mask(const void* p, int i, int is_u8)
{
    return is_u8 ? (((const unsigned char*)p)[i] != 0)
                 : (((const int*)p)[i] != 0);
}

// ---------------------------------------------------------------------------
// Prep: Qp = queries@Wq^T + bq ; KpK = keys@Wk^T + bk + abs_pos_K ;
//       VpV = keys@Wv^T + bv + abs_pos_V.
// 256 threads, 4 rows per block; W staged in padded smem (conflict-free).
// Block 0 additionally detects mask storage dtype (int32 vs uint8).
// ---------------------------------------------------------------------------
__global__ __launch_bounds__(256) void prep_kernel(
    const float* __restrict__ queries, const float* __restrict__ keys,
    const float* __restrict__ abs_pos_K, const float* __restrict__ abs_pos_V,
    const float* __restrict__ Wq, const float* __restrict__ bq,
    const float* __restrict__ Wk, const float* __restrict__ bk,
    const float* __restrict__ Wv, const float* __restrict__ bv,
    const unsigned int* __restrict__ am_words)
{
    const int t = threadIdx.x;

    if (blockIdx.x == 0 && t < 64) {
        // uint8 storage packs 4 random bools/word -> some word > 1 a.s.
        unsigned int bad = 0;
        for (int i = t; i < 256; i += 64) bad |= (am_words[i] > 1u);
        unsigned int any = __ballot_sync(0xffffffffu, bad != 0);
        if (t == 0) g_mask_is_u8 = (any != 0) ? 1 : 0;
    }

    __shared__ float Wqs[HH][HH + 1];
    __shared__ float Wks[HH][HH + 1];
    __shared__ float Wvs[HH][HH + 1];
    __shared__ float xq[ROWS_PB][HH];
    __shared__ float xk[ROWS_PB][HH];

#pragma unroll
    for (int i = 0; i < 16; ++i) {
        int idx = i * 256 + t;
        int r = idx >> 6, c = idx & 63;
        Wqs[r][c] = Wq[idx];
        Wks[r][c] = Wk[idx];
        Wvs[r][c] = Wv[idx];
    }

    const int r = t >> 6;
    const int c = t & 63;
    const int row = blockIdx.x * ROWS_PB + r;
    xq[r][c] = queries[row * HH + c];
    xk[r][c] = keys[row * HH + c];
    __syncthreads();

    float aq = 0.f, ak = 0.f, av = 0.f;
#pragma unroll 16
    for (int j = 0; j < HH; ++j) {
        float qv = xq[r][j], kv = xk[r][j];
        aq += qv * Wqs[c][j];
        ak += kv * Wks[c][j];
        av += kv * Wvs[c][j];
    }
    const int o = row * HH + c;
    g_Qp[o]  = aq + bq[c];
    g_KpK[o] = ak + bk[c] + abs_pos_K[o];
    g_VpV[o] = av + bv[c] + abs_pos_V[o];
}

// ---------------------------------------------------------------------------
// Fused attention with mask-aware load skipping.
// Masked (q,k): softmax weight is exactly 0 -> never load tK/dK/tV/dV there.
// time_mask[b,q]=1 (or all-masked row): uniform 1/L -> skip K phase entirely.
// ---------------------------------------------------------------------------
__global__ __launch_bounds__(256) void attn_kernel(
    const float* __restrict__ tK, const float* __restrict__ dK,
    const float* __restrict__ tV, const float* __restrict__ dV,
    const void* __restrict__ time_mask,
    const void* __restrict__ attn_mask,
    float* __restrict__ out)
{
    const int bq = blockIdx.x;
    const int b  = bq / LL;
    const int q  = bq % LL;
    const int t    = threadIdx.x;
    const int warp = t >> 5;
    const int lane = t & 31;

    __shared__ float s_p[NHEAD][LL];      // unnormalized probs at compacted idx
    __shared__ float s_inv[NHEAD];
    __shared__ short s_idx[LL];           // compacted unmasked k indices
    __shared__ int   s_woff[8];
    __shared__ int   s_M;
    __shared__ float4 s_red[16][16];

    const int is_u8 = g_mask_is_u8;
    const bool tmq = read_mask(time_mask, b * LL + q, is_u8);
    if (t == 0) s_M = 0;
    __syncthreads();

    // ---- deterministic stream compaction of unmasked k (skip if tmq) ----
    // NOTE: tmq is block-uniform, so the __syncthreads below are safe.
    if (!tmq) {
        const int k = t;
        const bool valid = (k < LL) && !read_mask(attn_mask, q * LL + k, is_u8);
        const unsigned bal = __ballot_sync(0xffffffffu, valid);
        if (lane == 0) s_woff[warp] = __popc(bal);
        __syncthreads();
        if (t == 0) {
            int acc = 0;
#pragma unroll
            for (int w = 0; w < 8; ++w) { int c0 = s_woff[w]; s_woff[w] = acc; acc += c0; }
            s_M = acc;
        }
        __syncthreads();
        if (valid)
            s_idx[s_woff[warp] + __popc(bal & ((1u << lane) - 1u))] = (short)k;
    }
    __syncthreads();
    const int  M = s_M;
    const bool uniform = (M == 0);        // tmq rows or fully-masked rows

    const float scale = 0.17677669529663687f;   // 1/sqrt(32)

    // ---- K phase over compacted list (skipped when uniform) ----
    // Warp-uniform trip count: loop over pair base jb (depends on warp only);
    // sub-half activity predicates only the smem write, never the shuffles.
    if (!uniform) {
        const int sub  = lane >> 4;
        const int idx4 = lane & 15;
        const int head = idx4 >> 3;

        const float4  q4   = ((const float4*)g_Qp + bq * 16)[idx4];
        const float4* tK4  = (const float4*)tK + (size_t)bq * LL * 16;
        const float4* dK4  = (const float4*)dK + (size_t)bq * LL * 16;
        const float4* KpK4 = (const float4*)g_KpK + b * LL * 16;

        for (int jb = warp * 2; jb < M; jb += 16) {
            const int  j   = jb + sub;
            const bool act = (j < M);
            const int  jj  = act ? j : jb;          // safe duplicate index
            const int  kk  = s_idx[jj];
            const int  o   = kk * 16 + idx4;
            float4 tv = __ldcs(tK4 + o);
            float4 dv = __ldcs(dK4 + o);
            float4 kp = KpK4[o];
            float p = (tv.x + dv.x + kp.x) * q4.x
                    + (tv.y + dv.y + kp.y) * q4.y
                    + (tv.z + dv.z + kp.z) * q4.z
                    + (tv.w + dv.w + kp.w) * q4.w;
            p += __shfl_xor_sync(0xffffffffu, p, 1);
            p += __shfl_xor_sync(0xffffffffu, p, 2);
            p += __shfl_xor_sync(0xffffffffu, p, 4);
            if (act && (lane & 7) == 0) s_p[head][j] = p * scale;
        }
    }
    __syncthreads();

    // ---- softmax over compacted entries: warp h handles head h ----
    // (per-lane loop trips differ but shuffles happen after loop exit: safe)
    if (!uniform && warp < NHEAD) {
        float m = -3.4e38f;
        for (int j = lane; j < M; j += 32) m = fmaxf(m, s_p[warp][j]);
#pragma unroll
        for (int s = 16; s > 0; s >>= 1)
            m = fmaxf(m, __shfl_xor_sync(0xffffffffu, m, s));
        float sum = 0.f;
        for (int j = lane; j < M; j += 32) {
            float e = __expf(s_p[warp][j] - m);
            s_p[warp][j] = e;
            sum += e;
        }
#pragma unroll
        for (int s = 16; s > 0; s >>= 1)
            sum += __shfl_xor_sync(0xffffffffu, sum, s);
        if (lane == 0) s_inv[warp] = 1.0f / sum;
    }
    __syncthreads();

    // ---- V phase (no shuffles; divergence is safe) ----
    {
        const int g    = t >> 4;
        const int idx4 = t & 15;
        const int head = idx4 >> 3;

        const float4* tV4  = (const float4*)tV + (size_t)bq * LL * 16;
        const float4* dV4  = (const float4*)dV + (size_t)bq * LL * 16;
        const float4* VpV4 = (const float4*)g_VpV + b * LL * 16;

        float4 acc = make_float4(0.f, 0.f, 0.f, 0.f);
        if (uniform) {
#pragma unroll 4
            for (int k = g; k < LL; k += 16) {
                const int o = k * 16 + idx4;
                float4 tv = __ldcs(tV4 + o);
                float4 dv = __ldcs(dV4 + o);
                float4 vp = VpV4[o];
                acc.x += tv.x + dv.x + vp.x;
                acc.y += tv.y + dv.y + vp.y;
                acc.z += tv.z + dv.z + vp.z;
                acc.w += tv.w + dv.w + vp.w;
            }
        } else {
#pragma unroll 4
            for (int j = g; j < M; j += 16) {
                const int kk = s_idx[j];
                const float a = s_p[head][j];
                const int o = kk * 16 + idx4;
                float4 tv = __ldcs(tV4 + o);
                float4 dv = __ldcs(dV4 + o);
                float4 vp = VpV4[o];
                acc.x += a * (tv.x + dv.x + vp.x);
                acc.y += a * (tv.y + dv.y + vp.y);
                acc.z += a * (tv.z + dv.z + vp.z);
                acc.w += a * (tv.w + dv.w + vp.w);
            }
        }
        s_red[g][idx4] = acc;
    }
    __syncthreads();

    if (t < HH) {
        const int idx4 = t >> 2;
        const int c    = t & 3;
        const float inv = uniform ? (1.0f / LL) : s_inv[t >> 5];
        float sum = 0.f;
#pragma unroll
        for (int g = 0; g < 16; ++g) {
            const float* v = (const float*)&s_red[g][idx4];
            sum += v[c];
        }
        out[bq * HH + t] = sum * inv;
    }
}

// ---------------------------------------------------------------------------
extern "C" void kernel_launch(void* const* d_in, const int* in_sizes, int n_in,
                              void* d_out, int out_size)
{
    const float* queries  = (const float*)d_in[0];
    const float* keys     = (const float*)d_in[1];
    const void*  time_mask = d_in[2];
    const void*  attn_mask = d_in[3];
    const float* tK = (const float*)d_in[4];
    const float* tV = (const float*)d_in[5];
    const float* dK = (const float*)d_in[6];
    const float* dV = (const float*)d_in[7];
    const float* abs_pos_K = (const float*)d_in[8];
    const float* abs_pos_V = (const float*)d_in[9];
    const float* Wq = (const float*)d_in[10];
    const float* bq = (const float*)d_in[11];
    const float* Wk = (const float*)d_in[12];
    const float* bk = (const float*)d_in[13];
    const float* Wv = (const float*)d_in[14];
    const float* bv = (const float*)d_in[15];
    float* out = (float*)d_out;

    prep_kernel<<<BB * LL / ROWS_PB, 256>>>(queries, keys, abs_pos_K, abs_pos_V,
                                            Wq, bq, Wk, bk, Wv, bv,
                                            (const unsigned int*)attn_mask);
    attn_kernel<<<BB * LL, 256>>>(tK, dK, tV, dV, time_mask, attn_mask, out);
}